// round 2
// baseline (speedup 1.0000x reference)
#include <cuda_runtime.h>
#include <cuda_bf16.h>
#include <math_constants.h>

// Problem constants (fixed by setup_inputs)
#define NPTS  16384
#define BATCH 8
#define M     2048
#define CH    128

#define CAP       3072          // per-batch bucket capacity (mean 2048, sd ~42; 24-sigma safe)
#define CHUNK_PTS 32            // points per block (8 warps x 4 points)
#define NCHUNKS   (CAP / CHUNK_PTS)   // 96

// Device scratch (no allocs allowed)
__device__ float  g_featsT[BATCH * M * CH];   // (B, m, C)
__device__ float4 g_known4[BATCH * M];        // coords padded to float4
__device__ int    g_bucket[BATCH * CAP];      // point ids grouped by batch
__device__ int    g_cnt[BATCH];               // per-batch counts

// ---------------------------------------------------------------------------
// Prep: zero counters + pack known coords (B,m,3) -> float4
// ---------------------------------------------------------------------------
__global__ void prep_kernel(const float* __restrict__ known)
{
    int i = blockIdx.x * blockDim.x + threadIdx.x;
    if (i < BATCH) g_cnt[i] = 0;
    if (i < BATCH * M) {
        float x = known[3 * i + 0];
        float y = known[3 * i + 1];
        float z = known[3 * i + 2];
        g_known4[i] = make_float4(x, y, z, 0.0f);
    }
}

// ---------------------------------------------------------------------------
// Transpose known_feats (B, C, m) -> g_featsT (B, m, C)
// ---------------------------------------------------------------------------
__global__ void transpose_feats_kernel(const float* __restrict__ in)
{
    __shared__ float tile[32][33];
    const int b  = blockIdx.z;
    const int j0 = blockIdx.x * 32;   // m dimension
    const int c0 = blockIdx.y * 32;   // channel dimension
    const int tx = threadIdx.x;
    const int ty = threadIdx.y;

    #pragma unroll
    for (int i = ty; i < 32; i += 8)
        tile[i][tx] = in[((size_t)(b * CH + c0 + i)) * M + j0 + tx];
    __syncthreads();
    #pragma unroll
    for (int i = ty; i < 32; i += 8)
        g_featsT[((size_t)(b * M + j0 + i)) * CH + c0 + tx] = tile[tx][i];
}

// ---------------------------------------------------------------------------
// Bucket points by batch. Bucket ORDER is nondeterministic (atomics) but the
// final output is invariant to it: every point's result depends only on its
// own data, and each point writes only its own output row.
// ---------------------------------------------------------------------------
__global__ void bucket_kernel(const int* __restrict__ batch_inds)
{
    __shared__ int hist[BATCH];
    __shared__ int base[BATCH];
    __shared__ int loc[BATCH];
    const int t = threadIdx.x;
    if (t < BATCH) { hist[t] = 0; loc[t] = 0; }
    __syncthreads();

    const int p = blockIdx.x * blockDim.x + t;   // 64 blocks x 256 = 16384
    const int b = batch_inds[p];
    atomicAdd(&hist[b], 1);
    __syncthreads();

    if (t < BATCH) base[t] = atomicAdd(&g_cnt[t], hist[t]);
    __syncthreads();

    const int r   = atomicAdd(&loc[b], 1);
    const int pos = base[b] + r;
    if (pos < CAP) g_bucket[b * CAP + pos] = p;
}

// ---------------------------------------------------------------------------
// Main kernel: block = (chunk of 32 points, batch). One batch's 2048 coords
// in 32KB smem; each warp handles 4 same-batch points, lanes stride the
// candidates so each LDS.128 feeds 4 top-3 trackers.
// ---------------------------------------------------------------------------
__global__ void __launch_bounds__(256)
knn_main_kernel(const float* __restrict__ unknown, float* __restrict__ out)
{
    __shared__ float4 sc[M];          // 32 KB
    const int b     = blockIdx.y;
    const int cnt   = g_cnt[b];
    const int start = blockIdx.x * CHUNK_PTS;
    if (start >= cnt) return;         // whole block exits together (pre-sync)

    const int t = threadIdx.x;
    const float4* __restrict__ src = g_known4 + b * M;
    #pragma unroll
    for (int i = t; i < M; i += 256) sc[i] = src[i];
    __syncthreads();

    const int lane = t & 31;
    const int w    = t >> 5;

    int   pid[4];
    float ux[4], uy[4], uz[4];
    #pragma unroll
    for (int k = 0; k < 4; k++) {
        const int ib = start + w * 4 + k;
        if (ib < cnt) {
            const int p = g_bucket[b * CAP + ib];
            pid[k] = p;
            ux[k] = unknown[p * 3 + 0];
            uy[k] = unknown[p * 3 + 1];
            uz[k] = unknown[p * 3 + 2];
        } else {
            pid[k] = -1;
            ux[k] = uy[k] = uz[k] = 0.0f;
        }
    }

    float d0[4], d1[4], d2[4];
    int   i0[4], i1[4], i2[4];
    #pragma unroll
    for (int k = 0; k < 4; k++) {
        d0[k] = d1[k] = d2[k] = CUDART_INF_F;
        i0[k] = i1[k] = i2[k] = 0;
    }

    #pragma unroll 2
    for (int j = lane; j < M; j += 32) {
        const float4 c = sc[j];
        #pragma unroll
        for (int k = 0; k < 4; k++) {
            const float dx = c.x - ux[k];
            const float dy = c.y - uy[k];
            const float dz = c.z - uz[k];
            const float d  = fmaf(dx, dx, fmaf(dy, dy, dz * dz));
            if (d < d2[k]) {
                if (d < d1[k]) {
                    d2[k] = d1[k]; i2[k] = i1[k];
                    if (d < d0[k]) { d1[k] = d0[k]; i1[k] = i0[k]; d0[k] = d; i0[k] = j; }
                    else           { d1[k] = d;     i1[k] = j; }
                } else { d2[k] = d; i2[k] = j; }
            }
        }
    }

    // Per-point warp merge of top-3 (64-bit keys: d2 bits || idx, ties -> lower idx)
    #pragma unroll
    for (int k = 0; k < 4; k++) {
        unsigned long long kl0 = ((unsigned long long)__float_as_uint(d0[k]) << 32) | (unsigned)i0[k];
        unsigned long long kl1 = ((unsigned long long)__float_as_uint(d1[k]) << 32) | (unsigned)i1[k];
        unsigned long long kl2 = ((unsigned long long)__float_as_uint(d2[k]) << 32) | (unsigned)i2[k];

        float wd[3]; int wi[3];
        int r = 0;
        #pragma unroll
        for (int s = 0; s < 3; s++) {
            unsigned long long v =
                (r == 0) ? kl0 : (r == 1) ? kl1 : (r == 2) ? kl2
                                                           : 0xFFFFFFFFFFFFFFFFull;
            const unsigned long long mine = v;
            #pragma unroll
            for (int off = 16; off; off >>= 1) {
                const unsigned long long o = __shfl_xor_sync(0xffffffffu, v, off);
                v = (o < v) ? o : v;
            }
            if (r < 3 && v == mine) r++;
            wd[s] = __uint_as_float((unsigned)(v >> 32));
            wi[s] = (int)(unsigned)(v & 0xffffffffu);
        }

        float w0 = 1.0f / (sqrtf(wd[0]) + 1e-8f);
        float w1 = 1.0f / (sqrtf(wd[1]) + 1e-8f);
        float w2 = 1.0f / (sqrtf(wd[2]) + 1e-8f);
        const float inv = 1.0f / (w0 + w1 + w2);
        w0 *= inv; w1 *= inv; w2 *= inv;

        const float4* f0 = (const float4*)(g_featsT + ((size_t)(b * M + wi[0])) * CH);
        const float4* f1 = (const float4*)(g_featsT + ((size_t)(b * M + wi[1])) * CH);
        const float4* f2 = (const float4*)(g_featsT + ((size_t)(b * M + wi[2])) * CH);

        const float4 a0 = f0[lane], a1 = f1[lane], a2 = f2[lane];
        float4 o;
        o.x = fmaf(w0, a0.x, fmaf(w1, a1.x, w2 * a2.x));
        o.y = fmaf(w0, a0.y, fmaf(w1, a1.y, w2 * a2.y));
        o.z = fmaf(w0, a0.z, fmaf(w1, a1.z, w2 * a2.z));
        o.w = fmaf(w0, a0.w, fmaf(w1, a1.w, w2 * a2.w));

        if (pid[k] >= 0)
            ((float4*)out)[(size_t)pid[k] * (CH / 4) + lane] = o;
    }
}

// ---------------------------------------------------------------------------
extern "C" void kernel_launch(void* const* d_in, const int* in_sizes, int n_in,
                              void* d_out, int out_size)
{
    const float* unknown     = (const float*)d_in[0];
    const float* known       = (const float*)d_in[1];
    const int*   batch_inds  = (const int*)d_in[2];
    const float* known_feats = (const float*)d_in[3];
    float* out = (float*)d_out;

    prep_kernel<<<(BATCH * M + 255) / 256, 256>>>(known);
    transpose_feats_kernel<<<dim3(M / 32, CH / 32, BATCH), dim3(32, 8)>>>(known_feats);
    bucket_kernel<<<NPTS / 256, 256>>>(batch_inds);
    knn_main_kernel<<<dim3(NCHUNKS, BATCH), 256>>>(unknown, out);
}